// round 5
// baseline (speedup 1.0000x reference)
#include <cuda_runtime.h>

// Problem constants (fixed shapes from setup_inputs)
#define BATCH 16
#define HH 512
#define WW 512
#define HW (HH * WW)
#define NPOLY 32
#define PPTS 128

#define NE 2048                     // LUT entries per table
#define HCLAMP 9.2102404f           // logit(1 - 1e-4)

#define FOCAL_BLOCKS 256            // 16 per batch image
#define AE_BLOCKS    256            // 2 polygons per block
#define TOTAL_BLOCKS (FOCAL_BLOCKS + AE_BLOCKS)

// Accumulators: zero-initialized at module load; the LAST block of every
// launch resets them after producing the output, so each graph replay starts
// from zeroed state. No prologue kernel needed.
__device__ float g_loss[BATCH];     // fused pos+neg focal loss sum per batch
__device__ float g_npos[BATCH];     // positive-pixel count per batch
__device__ float g_ae;              // sum of all point distances
__device__ int   g_done;            // completed-block counter

// ---------------------------------------------------------------------------
// Single fused kernel.
//   blocks [0, 256):   KP focal loss (16 blocks per batch image)
//   blocks [256, 512): AE loss (2 polygons per block)
// Last block to finish computes the final scalar and resets accumulators.
//
// Focal per pixel (branchless, after per-block LUT build):
//   pred = clip(sigmoid(h), 1e-4, 1-1e-4)  == sigmoid(clamp(h, +-HCLAMP))
//   neg (t != 1): 0.1*(1-t)^2 * [ sp * exp(-0.25*(sp-h)) ]      -> table A
//   pos (t == 1): 0.9        * [ (sp-h) * exp(-0.25*sp)  ]      -> table B
//   where sp = softplus(h).
// ---------------------------------------------------------------------------
__global__ __launch_bounds__(256) void main_kernel(
    const float* __restrict__ heat, const float* __restrict__ targ,
    const float* __restrict__ ae_map, const int* __restrict__ polys,
    float* __restrict__ out)
{
    __shared__ float2 stabA[NE];                // 16 KB  (val, slope)
    __shared__ float2 stabB[NE];                // 16 KB
    __shared__ float  red[16];
    __shared__ bool   last;

    if (blockIdx.x < FOCAL_BLOCKS) {
        // ------------------------- focal path ----------------------------
        const int b   = blockIdx.x >> 4;
        const int sub = blockIdx.x & 15;
        const float4* h4 = reinterpret_cast<const float4*>(heat + (size_t)b * HW);
        const float4* t4 = reinterpret_cast<const float4*>(targ + (size_t)b * HW);
        const int base = sub * 4096 + threadIdx.x;  // float4 idx within image

        // Prefetch first tile so DRAM latency overlaps the table build
        float4 hv0 = h4[base];
        float4 tv0 = t4[base];

        // ---- build LUT nodes (values into .x), fast-math, stable forms ----
        const float step = (2.0f * HCLAMP) / (float)(NE - 1);
        #pragma unroll
        for (int k = 0; k < 8; k++) {
            const int j = k * 256 + threadIdx.x;       // [0, 2048)
            float h  = fmaf((float)j, step, -HCLAMP);
            float ah = fabsf(h);
            float q  = __logf(1.0f + __expf(-ah));     // log1p(e^-|h|)
            float sp   = fmaxf(h, 0.0f) + q;           // softplus(h)
            float spmh = fmaxf(-h, 0.0f) + q;          // softplus(h) - h
            stabA[j].x = 0.1f * sp   * __expf(-0.25f * spmh);
            stabB[j].x = 0.9f * spmh * __expf(-0.25f * sp);
        }
        __syncthreads();
        // ---- slope pass (neighbor difference) ----
        #pragma unroll
        for (int k = 0; k < 8; k++) {
            const int j = k * 256 + threadIdx.x;
            float sA = (j < NE - 1) ? (stabA[j + 1].x - stabA[j].x) : 0.0f;
            float sB = (j < NE - 1) ? (stabB[j + 1].x - stabB[j].x) : 0.0f;
            stabA[j].y = sA;
            stabB[j].y = sB;
        }
        __syncthreads();

        const float SCALE = (float)(NE - 1) / (2.0f * HCLAMP);

        float lacc = 0.0f;
        float pacc = 0.0f;

        // This block covers float4 indices [sub*4096, (sub+1)*4096) of 65536
        #pragma unroll 4
        for (int k = 0; k < 16; k++) {
            float4 hv, tv;
            if (k == 0) { hv = hv0; tv = tv0; }
            else        { hv = h4[base + k * 256]; tv = t4[base + k * 256]; }
            float hs[4] = {hv.x, hv.y, hv.z, hv.w};
            float ts[4] = {tv.x, tv.y, tv.z, tv.w};
            #pragma unroll
            for (int j = 0; j < 4; j++) {
                float h = fminf(fmaxf(hs[j], -HCLAMP), HCLAMP);
                float t = ts[j];
                bool  pos = (t == 1.0f);

                float u  = (h + HCLAMP) * SCALE;        // [0, NE-1]
                int   ix = min((int)u, NE - 2);
                float fr = u - (float)ix;
                float w  = 1.0f - t;
                float wt = pos ? 1.0f : w * w;
                const float2* tb = pos ? stabB : stabA;
                float2 e = tb[ix];
                lacc = fmaf(wt, fmaf(fr, e.y, e.x), lacc);
                pacc += pos ? 1.0f : 0.0f;
            }
        }

        // Block reduction: 8 warps
        #pragma unroll
        for (int o = 16; o > 0; o >>= 1) {
            lacc += __shfl_down_sync(0xffffffffu, lacc, o);
            pacc += __shfl_down_sync(0xffffffffu, pacc, o);
        }
        const int warp = threadIdx.x >> 5, lane = threadIdx.x & 31;
        if (lane == 0) { red[warp] = lacc; red[8 + warp] = pacc; }
        __syncthreads();
        if (threadIdx.x == 0) {
            float tv2 = 0.0f, tp = 0.0f;
            #pragma unroll
            for (int w2 = 0; w2 < 8; w2++) { tv2 += red[w2]; tp += red[8 + w2]; }
            atomicAdd(&g_loss[b], tv2);
            atomicAdd(&g_npos[b], tp);
        }
    } else {
        // -------------------------- AE path ------------------------------
        // 2 polygons per block; warps 0-3 -> poly A, warps 4-7 -> poly B
        const int grp  = threadIdx.x >> 7;                      // 0 or 1
        const int p    = threadIdx.x & 127;                     // point index
        const int pid  = (blockIdx.x - FOCAL_BLOCKS) * 2 + grp; // b*NPOLY + n
        const int b    = pid >> 5;                              // NPOLY = 32
        const int wI   = threadIdx.x >> 5;                      // 0..7
        const int lane = threadIdx.x & 31;

        int2 yx = reinterpret_cast<const int2*>(polys)[pid * PPTS + p];
        const int y = yx.x;
        const int x = yx.y;

        // Center: exact integer sums over the 128 points of this polygon
        int sy = y, sx = x;
        #pragma unroll
        for (int o = 16; o > 0; o >>= 1) {
            sy += __shfl_down_sync(0xffffffffu, sy, o);
            sx += __shfl_down_sync(0xffffffffu, sx, o);
        }
        __shared__ int shy[8], shx[8];
        if (lane == 0) { shy[wI] = sy; shx[wI] = sx; }
        __syncthreads();
        const int w0 = grp * 4;
        const int toty = shy[w0] + shy[w0+1] + shy[w0+2] + shy[w0+3];
        const int totx = shx[w0] + shx[w0+1] + shx[w0+2] + shx[w0+3];
        const float cy = floorf((float)toty * (1.0f / 128.0f));  // exact
        const float cx = floorf((float)totx * (1.0f / 128.0f));

        // Gather ae_map[b, 0/1, y, x]; channel 0 pairs with y, 1 with x
        const float* bp = ae_map + (size_t)b * 2 * HW + (size_t)y * WW + x;
        const float g0 = bp[0];
        const float g1 = bp[HW];

        const float d0 = g0 + (float)y - cy;
        const float d1 = g1 + (float)x - cx;
        float dist = sqrtf(d0 * d0 + d1 * d1);

        #pragma unroll
        for (int o = 16; o > 0; o >>= 1)
            dist += __shfl_down_sync(0xffffffffu, dist, o);
        if (lane == 0) red[wI] = dist;
        __syncthreads();
        if (threadIdx.x == 0) {
            float tot = red[0] + red[1] + red[2] + red[3]
                      + red[4] + red[5] + red[6] + red[7];
            atomicAdd(&g_ae, tot);
        }
    }

    // ----------------- completion-counter finalize -----------------------
    // kp = mean_b( loss_sum_b / max(90 + 0.1*npos_b, 1) )
    // ae = 0.1 * ae_sum / (B*N*P)
    __threadfence();
    if (threadIdx.x == 0) {
        int d = atomicAdd(&g_done, 1);
        last = (d == TOTAL_BLOCKS - 1);
    }
    __syncthreads();
    if (last && threadIdx.x == 0) {
        const volatile float* vloss = g_loss;
        const volatile float* vnpos = g_npos;
        float kp = 0.0f;
        #pragma unroll
        for (int b2 = 0; b2 < BATCH; b2++) {
            float norm = fmaxf(90.0f + 0.1f * vnpos[b2], 1.0f);
            kp += vloss[b2] / norm;
        }
        kp *= (1.0f / (float)BATCH);
        float ae = 0.1f * (*(volatile float*)&g_ae)
                        * (1.0f / (float)(BATCH * NPOLY * PPTS));
        out[0] = kp + ae;

        // Reset accumulators for the next (graph-replayed) launch
        #pragma unroll
        for (int b2 = 0; b2 < BATCH; b2++) {
            g_loss[b2] = 0.0f;
            g_npos[b2] = 0.0f;
        }
        g_ae = 0.0f;
        __threadfence();
        g_done = 0;
    }
}

extern "C" void kernel_launch(void* const* d_in, const int* in_sizes, int n_in,
                              void* d_out, int out_size) {
    const float* kp_heat    = (const float*)d_in[0];  // [16,1,512,512] f32
    const float* ae_map     = (const float*)d_in[1];  // [16,2,512,512] f32
    const float* kp_targets = (const float*)d_in[2];  // [16,1,512,512] f32
    const int*   polygons   = (const int*)  d_in[3];  // [16,32,128,2] i32
    float* out = (float*)d_out;

    main_kernel<<<TOTAL_BLOCKS, 256>>>(kp_heat, kp_targets, ae_map, polygons, out);
}

// round 14
// speedup vs baseline: 1.1178x; 1.1178x over previous
#include <cuda_runtime.h>

// Problem constants (fixed shapes from setup_inputs)
#define BATCH 16
#define HH 512
#define WW 512
#define HW (HH * WW)
#define NPOLY 32
#define PPTS 128

#define NE 1024                     // LUT entries per table
#define HCLAMP 9.2102404f           // logit(1 - 1e-4)

#define FOCAL_BLOCKS 512            // 32 per batch image
#define AE_BLOCKS    256            // 2 polygons per block
#define TOTAL_BLOCKS (FOCAL_BLOCKS + AE_BLOCKS)

// Accumulators + LUTs; prologue kernel rebuilds/zeroes them every replay.
__device__ float  g_loss[BATCH];    // fused pos+neg focal loss sum per batch
__device__ float  g_npos[BATCH];    // positive-pixel count per batch
__device__ float  g_ae;             // sum of all point distances
__device__ int    g_done;           // completed-block counter
__device__ float2 g_tabA[NE];       // neg: (value, slope) of 0.1 * A(h)
__device__ float2 g_tabB[NE];       // pos: (value, slope) of 0.9 * B(h)

// sp = softplus(h); pred = sigmoid(h), clip implicit via clamp to +-HCLAMP
//   A(h) = sp * exp(-0.25*(sp-h))      (neg core, -pred^.25 * log(1-pred))
//   B(h) = (sp-h) * exp(-0.25*sp)      (pos core, -(1-pred)^.25 * log(pred))
// Stable split: q = log1p(exp(-|h|)); sp = max(h,0)+q; sp-h = max(-h,0)+q.
__device__ __forceinline__ void cores(float h, float& a, float& bb) {
    float q    = log1pf(expf(-fabsf(h)));    // precise libm (build only)
    float sp   = fmaxf(h, 0.0f) + q;
    float spmh = fmaxf(-h, 0.0f) + q;
    a  = 0.1f * sp   * expf(-0.25f * spmh);
    bb = 0.9f * spmh * expf(-0.25f * sp);
}

// ---------------------------------------------------------------------------
// Prologue: build both LUTs + zero accumulators.  4 blocks x 256 threads.
// Entry j needs core(h_j) and core(h_{j+1}); recompute both (cheap, 1 launch).
// ---------------------------------------------------------------------------
__global__ __launch_bounds__(256) void prologue_kernel() {
    const int j = blockIdx.x * 256 + threadIdx.x;   // [0, 1024)
    const float step = (2.0f * HCLAMP) / (float)(NE - 1);
    float h0 = fmaf((float)j, step, -HCLAMP);
    float a0, b0, a1, b1;
    cores(h0, a0, b0);
    cores(h0 + step, a1, b1);
    g_tabA[j] = make_float2(a0, a1 - a0);
    g_tabB[j] = make_float2(b0, b1 - b0);
    if (blockIdx.x == 0 && threadIdx.x < BATCH) {
        g_loss[threadIdx.x] = 0.0f;
        g_npos[threadIdx.x] = 0.0f;
        if (threadIdx.x == 0) { g_ae = 0.0f; g_done = 0; }
    }
}

// ---------------------------------------------------------------------------
// Main fused kernel.
//   blocks [0, 512):   KP focal loss (32 blocks per batch image)
//   blocks [512, 768): AE loss (2 polygons per block)
// Last block to finish computes the final scalar (threadfence + counter).
//
// Focal per pixel (branchless):
//   wt  = (t==1) ? 1 : (1-t)^2 ;  tab = (t==1) ? B : A
//   loss += wt * lerp(tab, clamp(h))
// ---------------------------------------------------------------------------
__global__ __launch_bounds__(256) void main_kernel(
    const float* __restrict__ heat, const float* __restrict__ targ,
    const float* __restrict__ ae_map, const int* __restrict__ polys,
    float* __restrict__ out)
{
    __shared__ float2 stabA[NE];                // 8 KB  (val, slope)
    __shared__ float2 stabB[NE];                // 8 KB
    __shared__ float  red[16];
    __shared__ bool   last;

    if (blockIdx.x < FOCAL_BLOCKS) {
        // ------------------------- focal path ----------------------------
        // Cooperative table copy: 2 x 1024 float2 = 2 x 512 float4
        {
            const float4* srcA = reinterpret_cast<const float4*>(g_tabA);
            const float4* srcB = reinterpret_cast<const float4*>(g_tabB);
            float4* dstA = reinterpret_cast<float4*>(stabA);
            float4* dstB = reinterpret_cast<float4*>(stabB);
            #pragma unroll
            for (int k = 0; k < 2; k++) {
                dstA[k * 256 + threadIdx.x] = srcA[k * 256 + threadIdx.x];
                dstB[k * 256 + threadIdx.x] = srcB[k * 256 + threadIdx.x];
            }
        }
        __syncthreads();

        const int b   = blockIdx.x >> 5;              // 32 blocks per image
        const int sub = blockIdx.x & 31;
        const float4* h4 = reinterpret_cast<const float4*>(heat + (size_t)b * HW);
        const float4* t4 = reinterpret_cast<const float4*>(targ + (size_t)b * HW);

        const float SCALE = (float)(NE - 1) / (2.0f * HCLAMP);

        float lacc = 0.0f;
        float pacc = 0.0f;

        // Block covers float4 indices [sub*2048, (sub+1)*2048) of 65536.
        // Full unroll -> 8 independent LDG.128 pairs batched up front (MLP).
        const int base = sub * 2048 + threadIdx.x;
        #pragma unroll
        for (int k = 0; k < 8; k++) {
            const int i = base + k * 256;
            float4 hv = h4[i];
            float4 tv = t4[i];
            float hs[4] = {hv.x, hv.y, hv.z, hv.w};
            float ts[4] = {tv.x, tv.y, tv.z, tv.w};
            #pragma unroll
            for (int j = 0; j < 4; j++) {
                float h = fminf(fmaxf(hs[j], -HCLAMP), HCLAMP);
                float t = ts[j];
                bool  pos = (t == 1.0f);

                float u  = (h + HCLAMP) * SCALE;        // [0, NE-1]
                int   ix = min((int)u, NE - 2);
                float fr = u - (float)ix;
                float w  = 1.0f - t;
                float wt = pos ? 1.0f : w * w;
                const float2* tb = pos ? stabB : stabA;
                float2 e = tb[ix];
                lacc = fmaf(wt, fmaf(fr, e.y, e.x), lacc);
                pacc += pos ? 1.0f : 0.0f;
            }
        }

        // Block reduction: 8 warps
        #pragma unroll
        for (int o = 16; o > 0; o >>= 1) {
            lacc += __shfl_down_sync(0xffffffffu, lacc, o);
            pacc += __shfl_down_sync(0xffffffffu, pacc, o);
        }
        const int warp = threadIdx.x >> 5, lane = threadIdx.x & 31;
        if (lane == 0) { red[warp] = lacc; red[8 + warp] = pacc; }
        __syncthreads();
        if (threadIdx.x == 0) {
            float tv2 = 0.0f, tp = 0.0f;
            #pragma unroll
            for (int w2 = 0; w2 < 8; w2++) { tv2 += red[w2]; tp += red[8 + w2]; }
            atomicAdd(&g_loss[b], tv2);
            atomicAdd(&g_npos[b], tp);
        }
    } else {
        // -------------------------- AE path ------------------------------
        // 2 polygons per block; warps 0-3 -> poly A, warps 4-7 -> poly B
        const int grp  = threadIdx.x >> 7;                      // 0 or 1
        const int p    = threadIdx.x & 127;                     // point index
        const int pid  = (blockIdx.x - FOCAL_BLOCKS) * 2 + grp; // b*NPOLY + n
        const int b    = pid >> 5;                              // NPOLY = 32
        const int wI   = threadIdx.x >> 5;                      // 0..7
        const int lane = threadIdx.x & 31;

        int2 yx = reinterpret_cast<const int2*>(polys)[pid * PPTS + p];
        const int y = yx.x;
        const int x = yx.y;

        // Center: exact integer sums over the 128 points of this polygon
        int sy = y, sx = x;
        #pragma unroll
        for (int o = 16; o > 0; o >>= 1) {
            sy += __shfl_down_sync(0xffffffffu, sy, o);
            sx += __shfl_down_sync(0xffffffffu, sx, o);
        }
        __shared__ int shy[8], shx[8];
        if (lane == 0) { shy[wI] = sy; shx[wI] = sx; }
        __syncthreads();
        const int w0 = grp * 4;
        const int toty = shy[w0] + shy[w0+1] + shy[w0+2] + shy[w0+3];
        const int totx = shx[w0] + shx[w0+1] + shx[w0+2] + shx[w0+3];
        const float cy = floorf((float)toty * (1.0f / 128.0f));  // exact
        const float cx = floorf((float)totx * (1.0f / 128.0f));

        // Gather ae_map[b, 0/1, y, x]; channel 0 pairs with y, 1 with x
        const float* bp = ae_map + (size_t)b * 2 * HW + (size_t)y * WW + x;
        const float g0 = bp[0];
        const float g1 = bp[HW];

        const float d0 = g0 + (float)y - cy;
        const float d1 = g1 + (float)x - cx;
        float dist = sqrtf(d0 * d0 + d1 * d1);

        #pragma unroll
        for (int o = 16; o > 0; o >>= 1)
            dist += __shfl_down_sync(0xffffffffu, dist, o);
        if (lane == 0) red[wI] = dist;
        __syncthreads();
        if (threadIdx.x == 0) {
            float tot = red[0] + red[1] + red[2] + red[3]
                      + red[4] + red[5] + red[6] + red[7];
            atomicAdd(&g_ae, tot);
        }
    }

    // ----------------- completion-counter finalize -----------------------
    // kp = mean_b( loss_sum_b / max(90 + 0.1*npos_b, 1) )
    // ae = 0.1 * ae_sum / (B*N*P)
    __threadfence();
    if (threadIdx.x == 0) {
        int d = atomicAdd(&g_done, 1);
        last = (d == TOTAL_BLOCKS - 1);
    }
    __syncthreads();
    if (last && threadIdx.x == 0) {
        const volatile float* vloss = g_loss;
        const volatile float* vnpos = g_npos;
        float kp = 0.0f;
        #pragma unroll
        for (int b2 = 0; b2 < BATCH; b2++) {
            float norm = fmaxf(90.0f + 0.1f * vnpos[b2], 1.0f);
            kp += vloss[b2] / norm;
        }
        kp *= (1.0f / (float)BATCH);
        float ae = 0.1f * (*(volatile float*)&g_ae)
                        * (1.0f / (float)(BATCH * NPOLY * PPTS));
        out[0] = kp + ae;
    }
}

extern "C" void kernel_launch(void* const* d_in, const int* in_sizes, int n_in,
                              void* d_out, int out_size) {
    const float* kp_heat    = (const float*)d_in[0];  // [16,1,512,512] f32
    const float* ae_map     = (const float*)d_in[1];  // [16,2,512,512] f32
    const float* kp_targets = (const float*)d_in[2];  // [16,1,512,512] f32
    const int*   polygons   = (const int*)  d_in[3];  // [16,32,128,2] i32
    float* out = (float*)d_out;

    prologue_kernel<<<4, 256>>>();
    main_kernel<<<TOTAL_BLOCKS, 256>>>(kp_heat, kp_targets, ae_map, polygons, out);
}